// round 4
// baseline (speedup 1.0000x reference)
#include <cuda_runtime.h>
#include <cuda_bf16.h>

// SDFVae per-part MLP, f32x2-packed (Blackwell fma.rn.f32x2).
//   d_in[0] points   [8,42,16384,3] f32
//   d_in[1] features [8,42*8]       f32
//   d_in[2] W0 [42,32,17]  d_in[3] W1 [42,32,32]
//   d_in[4] W2 [42,32,32]  d_in[5] W3 [42,1,32]
//   out [8,16384,42] f32
//
// Hidden dim (32) packed in pairs -> 16 f32x2 accumulators per layer.
// Weights staged TRANSPOSED in smem (sWT[d][k], k contiguous) so weight
// pairs load as uniform 64-bit LDS broadcasts. Activation h[d] broadcast
// into both packed halves once per d. Layer-0 feature term folded into a
// per-(b,p) bias (constant over n). f32x2 carriers are u64 with "l"
// constraints (matches ptx_helpers.cuh convention).

#define B_  8
#define P_  42
#define N_  16384
#define BLOCK 256

typedef unsigned long long u64;

__device__ __forceinline__ u64 ffma2(u64 a, u64 b, u64 c) {
    u64 d;
    asm("fma.rn.f32x2 %0, %1, %2, %3;" : "=l"(d) : "l"(a), "l"(b), "l"(c));
    return d;
}
__device__ __forceinline__ u64 pack2(float lo, float hi) {
    u64 r;
    asm("mov.b64 %0, {%1, %2};" : "=l"(r) : "f"(lo), "f"(hi));
    return r;
}
__device__ __forceinline__ u64 bcast2(float x) { return pack2(x, x); }
__device__ __forceinline__ void unpack2(u64 v, float& lo, float& hi) {
    asm("mov.b64 {%0, %1}, %2;" : "=f"(lo), "=f"(hi) : "l"(v));
}

__global__ __launch_bounds__(BLOCK, 2)
void sdfvae_mlp_kernel(const float* __restrict__ points,
                       const float* __restrict__ features,
                       const float* __restrict__ W0,
                       const float* __restrict__ W1,
                       const float* __restrict__ W2,
                       const float* __restrict__ W3,
                       float* __restrict__ out)
{
    const int b  = blockIdx.z;
    const int p  = blockIdx.y;
    const int n0 = blockIdx.x * BLOCK;
    const int tid = threadIdx.x;

    // Transposed weight tiles. W1/W2 rows padded to 36 floats (144B:
    // 16B-aligned, staging stores spread across banks).
    __shared__ __align__(16) float sW0T[9][32];    // [d][k], row 128B
    __shared__ __align__(16) float sB0[32];        // folded layer0 bias
    __shared__ __align__(16) float sW1T[32][36];   // [d][k]
    __shared__ __align__(16) float sW2T[32][36];
    __shared__ __align__(16) float sW3[32];

    const float* w0p = W0 + p * 32 * 17;
    for (int i = tid; i < 32 * 17; i += BLOCK) {
        int k = i / 17, d = i % 17;
        float v = w0p[i];
        if (d < 9) sW0T[d][k] = v;
    }
    const float* w1p = W1 + p * 1024;
    const float* w2p = W2 + p * 1024;
    for (int i = tid; i < 1024; i += BLOCK) {
        int k = i >> 5, d = i & 31;
        sW1T[d][k] = w1p[i];
        sW2T[d][k] = w2p[i];
    }
    if (tid < 32) {
        sW3[tid] = W3[p * 32 + tid];
        const float* f = features + (b * P_ + p) * 8;
        float acc = 0.f;
        #pragma unroll
        for (int j = 0; j < 8; j++)
            acc = fmaf(f[j], w0p[tid * 17 + 9 + j], acc);
        sB0[tid] = acc;
    }
    __syncthreads();

    const int n = n0 + tid;
    const float* pt = points + ((long long)(b * P_ + p) * N_ + n) * 3;
    float x = __ldg(pt + 0), y = __ldg(pt + 1), z = __ldg(pt + 2);

    float pe[9];
    pe[0] = x; pe[1] = y; pe[2] = z;
    __sincosf(x, &pe[3], &pe[6]);
    __sincosf(y, &pe[4], &pe[7]);
    __sincosf(z, &pe[5], &pe[8]);

    u64   acc[16];
    float ha[32], hb[32];

    // ---- layer 0: 9 pe dims, bias = folded features ----
    #pragma unroll
    for (int j = 0; j < 16; j++)
        acc[j] = *(const u64*)&sB0[2 * j];
    #pragma unroll
    for (int d = 0; d < 9; d++) {
        u64 bv = bcast2(pe[d]);
        const u64* wrow = (const u64*)&sW0T[d][0];
        #pragma unroll
        for (int j = 0; j < 16; j++)
            acc[j] = ffma2(wrow[j], bv, acc[j]);
    }
    #pragma unroll
    for (int j = 0; j < 16; j++) {
        float lo, hi; unpack2(acc[j], lo, hi);
        ha[2 * j]     = fmaxf(lo, 0.f);
        ha[2 * j + 1] = fmaxf(hi, 0.f);
    }

    // ---- layer 1 ----
    #pragma unroll
    for (int j = 0; j < 16; j++) acc[j] = 0ull;
    #pragma unroll
    for (int d = 0; d < 32; d++) {
        u64 bv = bcast2(ha[d]);
        const u64* wrow = (const u64*)&sW1T[d][0];
        #pragma unroll
        for (int j = 0; j < 16; j++)
            acc[j] = ffma2(wrow[j], bv, acc[j]);
    }
    #pragma unroll
    for (int j = 0; j < 16; j++) {
        float lo, hi; unpack2(acc[j], lo, hi);
        hb[2 * j]     = fmaxf(lo, 0.f);
        hb[2 * j + 1] = fmaxf(hi, 0.f);
    }

    // ---- layer 2 ----
    #pragma unroll
    for (int j = 0; j < 16; j++) acc[j] = 0ull;
    #pragma unroll
    for (int d = 0; d < 32; d++) {
        u64 bv = bcast2(hb[d]);
        const u64* wrow = (const u64*)&sW2T[d][0];
        #pragma unroll
        for (int j = 0; j < 16; j++)
            acc[j] = ffma2(wrow[j], bv, acc[j]);
    }
    #pragma unroll
    for (int j = 0; j < 16; j++) {
        float lo, hi; unpack2(acc[j], lo, hi);
        ha[2 * j]     = fmaxf(lo, 0.f);
        ha[2 * j + 1] = fmaxf(hi, 0.f);
    }

    // ---- layer 3: dot with w3 (pack over d, fold halves) ----
    u64 o2 = 0ull;
    const u64* w3p = (const u64*)&sW3[0];
    #pragma unroll
    for (int j = 0; j < 16; j++) {
        u64 hv = pack2(ha[2 * j], ha[2 * j + 1]);
        o2 = ffma2(w3p[j], hv, o2);
    }
    float olo, ohi; unpack2(o2, olo, ohi);
    float o = olo + ohi;

    out[((long long)b * N_ + n) * P_ + p] = o;
}

extern "C" void kernel_launch(void* const* d_in, const int* in_sizes, int n_in,
                              void* d_out, int out_size)
{
    const float* points   = (const float*)d_in[0];
    const float* features = (const float*)d_in[1];
    const float* W0       = (const float*)d_in[2];
    const float* W1       = (const float*)d_in[3];
    const float* W2       = (const float*)d_in[4];
    const float* W3       = (const float*)d_in[5];
    float* out = (float*)d_out;

    dim3 grid(N_ / BLOCK, P_, B_);
    sdfvae_mlp_kernel<<<grid, BLOCK>>>(points, features, W0, W1, W2, W3, out);
}

// round 5
// speedup vs baseline: 1.3380x; 1.3380x over previous
#include <cuda_runtime.h>
#include <cuda_bf16.h>

// SDFVae per-part MLP. f32x2-packed FMA + 2 points/thread so every weight
// LDS.128 is amortized over two FMA streams (R4 showed L1/LDS ~90% binding).
//   d_in[0] points   [8,42,16384,3] f32
//   d_in[1] features [8,42*8]       f32
//   d_in[2] W0 [42,32,17]  d_in[3] W1 [42,32,32]
//   d_in[4] W2 [42,32,32]  d_in[5] W3 [42,1,32]
//   out [8,16384,42] f32

#define B_  8
#define P_  42
#define N_  16384
#define BLOCK 256
#define MPT 2   // points per thread

typedef unsigned long long u64;

__device__ __forceinline__ u64 ffma2(u64 a, u64 b, u64 c) {
    u64 d;
    asm("fma.rn.f32x2 %0, %1, %2, %3;" : "=l"(d) : "l"(a), "l"(b), "l"(c));
    return d;
}
__device__ __forceinline__ u64 pack2(float lo, float hi) {
    u64 r;
    asm("mov.b64 %0, {%1, %2};" : "=l"(r) : "f"(lo), "f"(hi));
    return r;
}
__device__ __forceinline__ u64 bcast2(float x) { return pack2(x, x); }
__device__ __forceinline__ void unpack2(u64 v, float& lo, float& hi) {
    asm("mov.b64 {%0, %1}, %2;" : "=f"(lo), "=f"(hi) : "l"(v));
}

__global__ __launch_bounds__(BLOCK, 1)
void sdfvae_mlp_kernel(const float* __restrict__ points,
                       const float* __restrict__ features,
                       const float* __restrict__ W0,
                       const float* __restrict__ W1,
                       const float* __restrict__ W2,
                       const float* __restrict__ W3,
                       float* __restrict__ out)
{
    const int b  = blockIdx.z;
    const int p  = blockIdx.y;
    const int n0 = blockIdx.x * (BLOCK * MPT);
    const int tid = threadIdx.x;

    // Transposed weight tiles: sWT[d][k], k contiguous (packed pairs).
    // Rows padded to 36 floats (144B = 9*16B: keeps 16B alignment).
    __shared__ __align__(16) float sW0T[9][32];
    __shared__ __align__(16) float sB0[32];
    __shared__ __align__(16) float sW1T[32][36];
    __shared__ __align__(16) float sW2T[32][36];
    __shared__ __align__(16) float sW3[32];

    const float* w0p = W0 + p * 32 * 17;
    for (int i = tid; i < 32 * 17; i += BLOCK) {
        int k = i / 17, d = i % 17;
        float v = w0p[i];
        if (d < 9) sW0T[d][k] = v;
    }
    const float* w1p = W1 + p * 1024;
    const float* w2p = W2 + p * 1024;
    for (int i = tid; i < 1024; i += BLOCK) {
        int k = i >> 5, d = i & 31;
        sW1T[d][k] = w1p[i];
        sW2T[d][k] = w2p[i];
    }
    if (tid < 32) {
        sW3[tid] = W3[p * 32 + tid];
        const float* f = features + (b * P_ + p) * 8;
        float acc = 0.f;
        #pragma unroll
        for (int j = 0; j < 8; j++)
            acc = fmaf(f[j], w0p[tid * 17 + 9 + j], acc);
        sB0[tid] = acc;
    }
    __syncthreads();

    // two points: n and n + BLOCK (coalesced within each load wave)
    const long long base = (long long)(b * P_ + p) * N_;
    const int n_a = n0 + tid;
    const int n_b = n_a + BLOCK;

    float pe0[9], pe1[9];
    {
        const float* pa = points + (base + n_a) * 3;
        const float* pb = points + (base + n_b) * 3;
        float xa = __ldg(pa + 0), ya = __ldg(pa + 1), za = __ldg(pa + 2);
        float xb = __ldg(pb + 0), yb = __ldg(pb + 1), zb = __ldg(pb + 2);
        pe0[0] = xa; pe0[1] = ya; pe0[2] = za;
        pe1[0] = xb; pe1[1] = yb; pe1[2] = zb;
        __sincosf(xa, &pe0[3], &pe0[6]);
        __sincosf(ya, &pe0[4], &pe0[7]);
        __sincosf(za, &pe0[5], &pe0[8]);
        __sincosf(xb, &pe1[3], &pe1[6]);
        __sincosf(yb, &pe1[4], &pe1[7]);
        __sincosf(zb, &pe1[5], &pe1[8]);
    }

    u64   ac0[16], ac1[16];
    float h0a[32], h1a[32];   // point-a activations (ping/pong)
    float h0b[32], h1b[32];   // point-b activations

    // ---- layer 0 ----
    #pragma unroll
    for (int j = 0; j < 16; j++) {
        u64 bias = *(const u64*)&sB0[2 * j];
        ac0[j] = bias; ac1[j] = bias;
    }
    #pragma unroll
    for (int d = 0; d < 9; d++) {
        u64 v0 = bcast2(pe0[d]);
        u64 v1 = bcast2(pe1[d]);
        const ulonglong2* wr = (const ulonglong2*)&sW0T[d][0];
        #pragma unroll
        for (int jj = 0; jj < 8; jj++) {
            ulonglong2 w = wr[jj];            // LDS.128 broadcast
            ac0[2*jj]   = ffma2(w.x, v0, ac0[2*jj]);
            ac1[2*jj]   = ffma2(w.x, v1, ac1[2*jj]);
            ac0[2*jj+1] = ffma2(w.y, v0, ac0[2*jj+1]);
            ac1[2*jj+1] = ffma2(w.y, v1, ac1[2*jj+1]);
        }
    }
    #pragma unroll
    for (int j = 0; j < 16; j++) {
        float lo, hi;
        unpack2(ac0[j], lo, hi);
        h0a[2*j] = fmaxf(lo, 0.f); h0a[2*j+1] = fmaxf(hi, 0.f);
        unpack2(ac1[j], lo, hi);
        h0b[2*j] = fmaxf(lo, 0.f); h0b[2*j+1] = fmaxf(hi, 0.f);
    }

    // ---- layer 1 ----
    #pragma unroll
    for (int j = 0; j < 16; j++) { ac0[j] = 0ull; ac1[j] = 0ull; }
    #pragma unroll
    for (int d = 0; d < 32; d++) {
        u64 v0 = bcast2(h0a[d]);
        u64 v1 = bcast2(h0b[d]);
        const ulonglong2* wr = (const ulonglong2*)&sW1T[d][0];
        #pragma unroll
        for (int jj = 0; jj < 8; jj++) {
            ulonglong2 w = wr[jj];
            ac0[2*jj]   = ffma2(w.x, v0, ac0[2*jj]);
            ac1[2*jj]   = ffma2(w.x, v1, ac1[2*jj]);
            ac0[2*jj+1] = ffma2(w.y, v0, ac0[2*jj+1]);
            ac1[2*jj+1] = ffma2(w.y, v1, ac1[2*jj+1]);
        }
    }
    #pragma unroll
    for (int j = 0; j < 16; j++) {
        float lo, hi;
        unpack2(ac0[j], lo, hi);
        h1a[2*j] = fmaxf(lo, 0.f); h1a[2*j+1] = fmaxf(hi, 0.f);
        unpack2(ac1[j], lo, hi);
        h1b[2*j] = fmaxf(lo, 0.f); h1b[2*j+1] = fmaxf(hi, 0.f);
    }

    // ---- layer 2 ----
    #pragma unroll
    for (int j = 0; j < 16; j++) { ac0[j] = 0ull; ac1[j] = 0ull; }
    #pragma unroll
    for (int d = 0; d < 32; d++) {
        u64 v0 = bcast2(h1a[d]);
        u64 v1 = bcast2(h1b[d]);
        const ulonglong2* wr = (const ulonglong2*)&sW2T[d][0];
        #pragma unroll
        for (int jj = 0; jj < 8; jj++) {
            ulonglong2 w = wr[jj];
            ac0[2*jj]   = ffma2(w.x, v0, ac0[2*jj]);
            ac1[2*jj]   = ffma2(w.x, v1, ac1[2*jj]);
            ac0[2*jj+1] = ffma2(w.y, v0, ac0[2*jj+1]);
            ac1[2*jj+1] = ffma2(w.y, v1, ac1[2*jj+1]);
        }
    }
    #pragma unroll
    for (int j = 0; j < 16; j++) {
        float lo, hi;
        unpack2(ac0[j], lo, hi);
        h0a[2*j] = fmaxf(lo, 0.f); h0a[2*j+1] = fmaxf(hi, 0.f);
        unpack2(ac1[j], lo, hi);
        h0b[2*j] = fmaxf(lo, 0.f); h0b[2*j+1] = fmaxf(hi, 0.f);
    }

    // ---- layer 3: dot with w3 ----
    u64 oa = 0ull, ob = 0ull;
    {
        const ulonglong2* wr = (const ulonglong2*)&sW3[0];
        #pragma unroll
        for (int jj = 0; jj < 8; jj++) {
            ulonglong2 w = wr[jj];
            oa = ffma2(w.x, pack2(h0a[4*jj],   h0a[4*jj+1]), oa);
            ob = ffma2(w.x, pack2(h0b[4*jj],   h0b[4*jj+1]), ob);
            oa = ffma2(w.y, pack2(h0a[4*jj+2], h0a[4*jj+3]), oa);
            ob = ffma2(w.y, pack2(h0b[4*jj+2], h0b[4*jj+3]), ob);
        }
    }
    float lo, hi;
    unpack2(oa, lo, hi);
    float out_a = lo + hi;
    unpack2(ob, lo, hi);
    float out_b = lo + hi;

    out[((long long)b * N_ + n_a) * P_ + p] = out_a;
    out[((long long)b * N_ + n_b) * P_ + p] = out_b;
}

extern "C" void kernel_launch(void* const* d_in, const int* in_sizes, int n_in,
                              void* d_out, int out_size)
{
    const float* points   = (const float*)d_in[0];
    const float* features = (const float*)d_in[1];
    const float* W0       = (const float*)d_in[2];
    const float* W1       = (const float*)d_in[3];
    const float* W2       = (const float*)d_in[4];
    const float* W3       = (const float*)d_in[5];
    float* out = (float*)d_out;

    dim3 grid(N_ / (BLOCK * MPT), P_, B_);
    sdfvae_mlp_kernel<<<grid, BLOCK>>>(points, features, W0, W1, W2, W3, out);
}

// round 6
// speedup vs baseline: 1.4117x; 1.0551x over previous
#include <cuda_runtime.h>
#include <cuda_bf16.h>

// SDFVae per-part MLP. f32x2 FMA + 2 points/thread; BLOCK=128 with
// min-3-CTAs-per-SM to raise warps/SMSP 2->3 (R5 was stall-bound at
// occ=12%, fma=54%).
//   d_in[0] points   [8,42,16384,3] f32
//   d_in[1] features [8,42*8]       f32
//   d_in[2] W0 [42,32,17]  d_in[3] W1 [42,32,32]
//   d_in[4] W2 [42,32,32]  d_in[5] W3 [42,1,32]
//   out [8,16384,42] f32

#define B_  8
#define P_  42
#define N_  16384
#define BLOCK 128
#define MPT 2   // points per thread

typedef unsigned long long u64;

__device__ __forceinline__ u64 ffma2(u64 a, u64 b, u64 c) {
    u64 d;
    asm("fma.rn.f32x2 %0, %1, %2, %3;" : "=l"(d) : "l"(a), "l"(b), "l"(c));
    return d;
}
__device__ __forceinline__ u64 pack2(float lo, float hi) {
    u64 r;
    asm("mov.b64 %0, {%1, %2};" : "=l"(r) : "f"(lo), "f"(hi));
    return r;
}
__device__ __forceinline__ u64 bcast2(float x) { return pack2(x, x); }
__device__ __forceinline__ void unpack2(u64 v, float& lo, float& hi) {
    asm("mov.b64 {%0, %1}, %2;" : "=f"(lo), "=f"(hi) : "l"(v));
}

__global__ __launch_bounds__(BLOCK, 3)
void sdfvae_mlp_kernel(const float* __restrict__ points,
                       const float* __restrict__ features,
                       const float* __restrict__ W0,
                       const float* __restrict__ W1,
                       const float* __restrict__ W2,
                       const float* __restrict__ W3,
                       float* __restrict__ out)
{
    const int b  = blockIdx.z;
    const int p  = blockIdx.y;
    const int n0 = blockIdx.x * (BLOCK * MPT);
    const int tid = threadIdx.x;

    // Transposed weight tiles: sWT[d][k], k contiguous (packed pairs).
    // W1/W2 rows padded to 36 floats (144B = 9*16B: keeps 16B alignment).
    __shared__ __align__(16) float sW0T[9][32];
    __shared__ __align__(16) float sB0[32];
    __shared__ __align__(16) float sW1T[32][36];
    __shared__ __align__(16) float sW2T[32][36];
    __shared__ __align__(16) float sW3[32];

    const float* w0p = W0 + p * 32 * 17;
    for (int i = tid; i < 32 * 17; i += BLOCK) {
        int k = i / 17, d = i % 17;
        float v = w0p[i];
        if (d < 9) sW0T[d][k] = v;
    }
    const float* w1p = W1 + p * 1024;
    const float* w2p = W2 + p * 1024;
    for (int i = tid; i < 1024; i += BLOCK) {
        int k = i >> 5, d = i & 31;
        sW1T[d][k] = w1p[i];
        sW2T[d][k] = w2p[i];
    }
    if (tid < 32) {
        sW3[tid] = W3[p * 32 + tid];
        const float* f = features + (b * P_ + p) * 8;
        float acc = 0.f;
        #pragma unroll
        for (int j = 0; j < 8; j++)
            acc = fmaf(f[j], w0p[tid * 17 + 9 + j], acc);
        sB0[tid] = acc;
    }
    __syncthreads();

    // two points: n and n + BLOCK (coalesced within each load wave)
    const long long base = (long long)(b * P_ + p) * N_;
    const int n_a = n0 + tid;
    const int n_b = n_a + BLOCK;

    float pe0[9], pe1[9];
    {
        const float* pa = points + (base + n_a) * 3;
        const float* pb = points + (base + n_b) * 3;
        float xa = __ldg(pa + 0), ya = __ldg(pa + 1), za = __ldg(pa + 2);
        float xb = __ldg(pb + 0), yb = __ldg(pb + 1), zb = __ldg(pb + 2);
        pe0[0] = xa; pe0[1] = ya; pe0[2] = za;
        pe1[0] = xb; pe1[1] = yb; pe1[2] = zb;
        __sincosf(xa, &pe0[3], &pe0[6]);
        __sincosf(ya, &pe0[4], &pe0[7]);
        __sincosf(za, &pe0[5], &pe0[8]);
        __sincosf(xb, &pe1[3], &pe1[6]);
        __sincosf(yb, &pe1[4], &pe1[7]);
        __sincosf(zb, &pe1[5], &pe1[8]);
    }

    u64   ac0[16], ac1[16];
    float h0a[32], h1a[32];   // point-a activations (ping/pong)
    float h0b[32], h1b[32];   // point-b activations

    // ---- layer 0 ----
    #pragma unroll
    for (int j = 0; j < 16; j++) {
        u64 bias = *(const u64*)&sB0[2 * j];
        ac0[j] = bias; ac1[j] = bias;
    }
    #pragma unroll
    for (int d = 0; d < 9; d++) {
        u64 v0 = bcast2(pe0[d]);
        u64 v1 = bcast2(pe1[d]);
        const ulonglong2* wr = (const ulonglong2*)&sW0T[d][0];
        #pragma unroll
        for (int jj = 0; jj < 8; jj++) {
            ulonglong2 w = wr[jj];            // LDS.128 broadcast
            ac0[2*jj]   = ffma2(w.x, v0, ac0[2*jj]);
            ac1[2*jj]   = ffma2(w.x, v1, ac1[2*jj]);
            ac0[2*jj+1] = ffma2(w.y, v0, ac0[2*jj+1]);
            ac1[2*jj+1] = ffma2(w.y, v1, ac1[2*jj+1]);
        }
    }
    #pragma unroll
    for (int j = 0; j < 16; j++) {
        float lo, hi;
        unpack2(ac0[j], lo, hi);
        h0a[2*j] = fmaxf(lo, 0.f); h0a[2*j+1] = fmaxf(hi, 0.f);
        unpack2(ac1[j], lo, hi);
        h0b[2*j] = fmaxf(lo, 0.f); h0b[2*j+1] = fmaxf(hi, 0.f);
    }

    // ---- layer 1 ----
    #pragma unroll
    for (int j = 0; j < 16; j++) { ac0[j] = 0ull; ac1[j] = 0ull; }
    #pragma unroll
    for (int d = 0; d < 32; d++) {
        u64 v0 = bcast2(h0a[d]);
        u64 v1 = bcast2(h0b[d]);
        const ulonglong2* wr = (const ulonglong2*)&sW1T[d][0];
        #pragma unroll
        for (int jj = 0; jj < 8; jj++) {
            ulonglong2 w = wr[jj];
            ac0[2*jj]   = ffma2(w.x, v0, ac0[2*jj]);
            ac1[2*jj]   = ffma2(w.x, v1, ac1[2*jj]);
            ac0[2*jj+1] = ffma2(w.y, v0, ac0[2*jj+1]);
            ac1[2*jj+1] = ffma2(w.y, v1, ac1[2*jj+1]);
        }
    }
    #pragma unroll
    for (int j = 0; j < 16; j++) {
        float lo, hi;
        unpack2(ac0[j], lo, hi);
        h1a[2*j] = fmaxf(lo, 0.f); h1a[2*j+1] = fmaxf(hi, 0.f);
        unpack2(ac1[j], lo, hi);
        h1b[2*j] = fmaxf(lo, 0.f); h1b[2*j+1] = fmaxf(hi, 0.f);
    }

    // ---- layer 2 ----
    #pragma unroll
    for (int j = 0; j < 16; j++) { ac0[j] = 0ull; ac1[j] = 0ull; }
    #pragma unroll
    for (int d = 0; d < 32; d++) {
        u64 v0 = bcast2(h1a[d]);
        u64 v1 = bcast2(h1b[d]);
        const ulonglong2* wr = (const ulonglong2*)&sW2T[d][0];
        #pragma unroll
        for (int jj = 0; jj < 8; jj++) {
            ulonglong2 w = wr[jj];
            ac0[2*jj]   = ffma2(w.x, v0, ac0[2*jj]);
            ac1[2*jj]   = ffma2(w.x, v1, ac1[2*jj]);
            ac0[2*jj+1] = ffma2(w.y, v0, ac0[2*jj+1]);
            ac1[2*jj+1] = ffma2(w.y, v1, ac1[2*jj+1]);
        }
    }
    #pragma unroll
    for (int j = 0; j < 16; j++) {
        float lo, hi;
        unpack2(ac0[j], lo, hi);
        h0a[2*j] = fmaxf(lo, 0.f); h0a[2*j+1] = fmaxf(hi, 0.f);
        unpack2(ac1[j], lo, hi);
        h0b[2*j] = fmaxf(lo, 0.f); h0b[2*j+1] = fmaxf(hi, 0.f);
    }

    // ---- layer 3: dot with w3 ----
    u64 oa = 0ull, ob = 0ull;
    {
        const ulonglong2* wr = (const ulonglong2*)&sW3[0];
        #pragma unroll
        for (int jj = 0; jj < 8; jj++) {
            ulonglong2 w = wr[jj];
            oa = ffma2(w.x, pack2(h0a[4*jj],   h0a[4*jj+1]), oa);
            ob = ffma2(w.x, pack2(h0b[4*jj],   h0b[4*jj+1]), ob);
            oa = ffma2(w.y, pack2(h0a[4*jj+2], h0a[4*jj+3]), oa);
            ob = ffma2(w.y, pack2(h0b[4*jj+2], h0b[4*jj+3]), ob);
        }
    }
    float lo, hi;
    unpack2(oa, lo, hi);
    float out_a = lo + hi;
    unpack2(ob, lo, hi);
    float out_b = lo + hi;

    out[((long long)b * N_ + n_a) * P_ + p] = out_a;
    out[((long long)b * N_ + n_b) * P_ + p] = out_b;
}

extern "C" void kernel_launch(void* const* d_in, const int* in_sizes, int n_in,
                              void* d_out, int out_size)
{
    const float* points   = (const float*)d_in[0];
    const float* features = (const float*)d_in[1];
    const float* W0       = (const float*)d_in[2];
    const float* W1       = (const float*)d_in[3];
    const float* W2       = (const float*)d_in[4];
    const float* W3       = (const float*)d_in[5];
    float* out = (float*)d_out;

    dim3 grid(N_ / (BLOCK * MPT), P_, B_);
    sdfvae_mlp_kernel<<<grid, BLOCK>>>(points, features, W0, W1, W2, W3, out);
}

// round 8
// speedup vs baseline: 3.2184x; 2.2799x over previous
#include <cuda_runtime.h>
#include <cuda_bf16.h>
#include <cstdint>

// SDFVae per-part MLP on mma.sync.m16n8k16 (bf16 hi+mid split, f32 accum).
// tcgen05 unavailable (harness targets sm_100 without 'a'); warp-level MMA
// chains layers in registers via the C-frag == A-frag-half identity.
//   d_in[0] points [8,42,16384,3] f32   d_in[1] features [8,336] f32
//   d_in[2] W0 [42,32,17]  d_in[3] W1 [42,32,32]
//   d_in[4] W2 [42,32,32]  d_in[5] W3 [42,1,32]
//   out [8,16384,42] f32

#define B_ 8
#define P_ 42
#define N_ 16384
#define THREADS 128
#define CHUNK 2048
#define ITERS (CHUNK / 128)   // 16

__device__ __forceinline__ void mma16816(float c[4],
    uint32_t a0, uint32_t a1, uint32_t a2, uint32_t a3,
    uint32_t b0, uint32_t b1)
{
    asm volatile(
        "mma.sync.aligned.m16n8k16.row.col.f32.bf16.bf16.f32 "
        "{%0,%1,%2,%3}, {%4,%5,%6,%7}, {%8,%9}, {%0,%1,%2,%3};"
        : "+f"(c[0]), "+f"(c[1]), "+f"(c[2]), "+f"(c[3])
        : "r"(a0), "r"(a1), "r"(a2), "r"(a3), "r"(b0), "r"(b1));
}
// bf16x2 {lo,hi} from two f32 (round-to-nearest)
__device__ __forceinline__ uint32_t pack_rn(float lo, float hi) {
    uint32_t r;
    asm("cvt.rn.satfinite.bf16x2.f32 %0, %1, %2;" : "=r"(r) : "f"(hi), "f"(lo));
    return r;
}
// bf16x2 {lo,hi} by truncating top 16 bits of each f32 (1 PRMT)
__device__ __forceinline__ uint32_t pack_hi16(float lo, float hi) {
    return __byte_perm(__float_as_uint(lo), __float_as_uint(hi), 0x7632);
}
__device__ __forceinline__ float trunc_bf(float v) {
    return __uint_as_float(__float_as_uint(v) & 0xFFFF0000u);
}
__device__ __forceinline__ float rn_bf(float v) {
    return __bfloat162float(__float2bfloat16(v));
}

__global__ __launch_bounds__(THREADS)
void sdfvae_mma_kernel(const float* __restrict__ points,
                       const float* __restrict__ features,
                       const float* __restrict__ W0,
                       const float* __restrict__ W1,
                       const float* __restrict__ W2,
                       const float* __restrict__ W3,
                       float* __restrict__ out)
{
    const int chunk = blockIdx.x, p = blockIdx.y, b = blockIdx.z;
    const int tid = threadIdx.x;
    const int w = tid >> 5, lane = tid & 31;
    const int g = lane >> 2, q = lane & 3;   // groupID, thread-in-group

    // per-warp pe staging: [warp][row][pair] (pairs 0..7 used, pad 9)
    __shared__ uint32_t sPEh[4][32][9];
    __shared__ uint32_t sPEm[4][32][9];

    // ---------------- B fragments (once per CTA, from gmem) ----------------
    // PTX m16n8k16 B (col-major KxN): b0 = {B[2q][n], B[2q+1][n]}, b1 = k+8,
    // n = g (+8*ntile). B[k][n] = W[n][k].
    uint32_t b0h[4][2], b0m[4][2];         // L0  [ntile][b0,b1] (kb=0 only)
    uint32_t b1h[4][2][2], b1m[4][2][2];   // L1  [ntile][kb][b0,b1]
    uint32_t b2h[4][2][2], b2m[4][2][2];   // L2
    uint32_t b3h[2][2], b3m[2][2];         // L3  [kb][b0,b1] (n-tile 0 only)

    const float* W0p = W0 + p * 32 * 17;
    const float* fv  = features + (b * P_ + p) * 8;

    #pragma unroll
    for (int j = 0; j < 4; j++) {
        const int n = g + 8 * j;
        const float* w0r = W0p + n * 17;
        float bias = 0.f;
        #pragma unroll
        for (int t = 0; t < 8; t++) bias = fmaf(fv[t], w0r[9 + t], bias);

        // L0 b0: k = 2q, 2q+1  (<= 7, always real pe cols)
        float v0 = w0r[2 * q], v1 = w0r[2 * q + 1];
        b0h[j][0] = pack_rn(rn_bf(v0), rn_bf(v1));
        b0m[j][0] = pack_rn(v0 - rn_bf(v0), v1 - rn_bf(v1));
        // L0 b1: k = 2q+8, 2q+9 : q==0 -> (W0[.,8], bias); q>0 -> k>=10 -> 0
        if (q == 0) {
            float u0 = w0r[8], u1 = bias;
            b0h[j][1] = pack_rn(rn_bf(u0), rn_bf(u1));
            b0m[j][1] = pack_rn(u0 - rn_bf(u0), u1 - rn_bf(u1));
        } else {
            b0h[j][1] = 0u; b0m[j][1] = 0u;
        }

        const float* w1r = W1 + p * 1024 + n * 32;
        const float* w2r = W2 + p * 1024 + n * 32;
        #pragma unroll
        for (int kb = 0; kb < 2; kb++) {
            int k0 = 2 * q + 16 * kb;
            float a0 = w1r[k0], a1 = w1r[k0 + 1], a2 = w1r[k0 + 8], a3 = w1r[k0 + 9];
            b1h[j][kb][0] = pack_rn(rn_bf(a0), rn_bf(a1));
            b1m[j][kb][0] = pack_rn(a0 - rn_bf(a0), a1 - rn_bf(a1));
            b1h[j][kb][1] = pack_rn(rn_bf(a2), rn_bf(a3));
            b1m[j][kb][1] = pack_rn(a2 - rn_bf(a2), a3 - rn_bf(a3));
            float c0 = w2r[k0], c1 = w2r[k0 + 1], c2 = w2r[k0 + 8], c3 = w2r[k0 + 9];
            b2h[j][kb][0] = pack_rn(rn_bf(c0), rn_bf(c1));
            b2m[j][kb][0] = pack_rn(c0 - rn_bf(c0), c1 - rn_bf(c1));
            b2h[j][kb][1] = pack_rn(rn_bf(c2), rn_bf(c3));
            b2m[j][kb][1] = pack_rn(c2 - rn_bf(c2), c3 - rn_bf(c3));
        }
    }
    {
        const float* w3r = W3 + p * 32;
        #pragma unroll
        for (int kb = 0; kb < 2; kb++) {
            int k0 = 2 * q + 16 * kb;
            if (g == 0) {   // only n==0 column is real
                float a0 = w3r[k0], a1 = w3r[k0 + 1], a2 = w3r[k0 + 8], a3 = w3r[k0 + 9];
                b3h[kb][0] = pack_rn(rn_bf(a0), rn_bf(a1));
                b3m[kb][0] = pack_rn(a0 - rn_bf(a0), a1 - rn_bf(a1));
                b3h[kb][1] = pack_rn(rn_bf(a2), rn_bf(a3));
                b3m[kb][1] = pack_rn(a2 - rn_bf(a2), a3 - rn_bf(a3));
            } else {
                b3h[kb][0] = b3h[kb][1] = 0u;
                b3m[kb][0] = b3m[kb][1] = 0u;
            }
        }
    }

    const long long pbase = (long long)(b * P_ + p) * N_ + (long long)chunk * CHUNK;
    const long long obase = (long long)b * N_ + (long long)chunk * CHUNK;

    for (int it = 0; it < ITERS; it++) {
        const int mwarp = it * 128 + w * 32;     // warp's first point (local)

        // ---- pe compute + stage (each lane = its own point = row `lane`) ----
        __syncwarp();
        {
            const float* pt = points + (pbase + mwarp + lane) * 3;
            float x = __ldg(pt), y = __ldg(pt + 1), z = __ldg(pt + 2);
            float v[10];
            v[0] = x; v[1] = y; v[2] = z;
            __sincosf(x, &v[3], &v[6]);
            __sincosf(y, &v[4], &v[7]);
            __sincosf(z, &v[5], &v[8]);
            v[9] = 1.f;   // bias input dim
            #pragma unroll
            for (int t = 0; t < 5; t++) {
                float a = v[2 * t], c = v[2 * t + 1];
                sPEh[w][lane][t] = pack_rn(rn_bf(a), rn_bf(c));
                sPEm[w][lane][t] = pack_rn(a - rn_bf(a), c - rn_bf(c));
            }
            #pragma unroll
            for (int t = 5; t < 8; t++) {
                sPEh[w][lane][t] = 0u;
                sPEm[w][lane][t] = 0u;
            }
        }
        __syncwarp();

        #pragma unroll
        for (int mt = 0; mt < 2; mt++) {
            const int rbase = mt * 16;

            // A0 frags (PTX m16n8k16 A row-major): a0=(g,2q..), a1=(g+8,..),
            // a2=(g, 2q+8..) -> pair q+4, a3=(g+8, pair q+4)
            uint32_t A0h0 = sPEh[w][rbase + g][q];
            uint32_t A0h1 = sPEh[w][rbase + g + 8][q];
            uint32_t A0h2 = sPEh[w][rbase + g][q + 4];
            uint32_t A0h3 = sPEh[w][rbase + g + 8][q + 4];
            uint32_t A0m0 = sPEm[w][rbase + g][q];
            uint32_t A0m1 = sPEm[w][rbase + g + 8][q];
            uint32_t A0m2 = sPEm[w][rbase + g][q + 4];
            uint32_t A0m3 = sPEm[w][rbase + g + 8][q + 4];

            float C[4][4];
            #pragma unroll
            for (int n = 0; n < 4; n++)
                C[n][0] = C[n][1] = C[n][2] = C[n][3] = 0.f;

            // ---- L0 (K=16): 3 split terms ----
            #pragma unroll
            for (int n = 0; n < 4; n++) {
                mma16816(C[n], A0h0, A0h1, A0h2, A0h3, b0h[n][0], b0h[n][1]);
                mma16816(C[n], A0m0, A0m1, A0m2, A0m3, b0h[n][0], b0h[n][1]);
                mma16816(C[n], A0h0, A0h1, A0h2, A0h3, b0m[n][0], b0m[n][1]);
            }

            uint32_t Ah[2][4], Am[2][4];
            // transition: relu + split; C ntile n -> A kb=n/2, regs (n&1)*2..
            #pragma unroll
            for (int n = 0; n < 4; n++) {
                float c0 = fmaxf(C[n][0], 0.f), c1 = fmaxf(C[n][1], 0.f);
                float c2 = fmaxf(C[n][2], 0.f), c3 = fmaxf(C[n][3], 0.f);
                int kb = n >> 1, pos = (n & 1) * 2;
                Ah[kb][pos]     = pack_hi16(c0, c1);
                Ah[kb][pos + 1] = pack_hi16(c2, c3);
                Am[kb][pos]     = pack_rn(c0 - trunc_bf(c0), c1 - trunc_bf(c1));
                Am[kb][pos + 1] = pack_rn(c2 - trunc_bf(c2), c3 - trunc_bf(c3));
            }

            // ---- L1 (K=32) ----
            #pragma unroll
            for (int n = 0; n < 4; n++)
                C[n][0] = C[n][1] = C[n][2] = C[n][3] = 0.f;
            #pragma unroll
            for (int n = 0; n < 4; n++) {
                #pragma unroll
                for (int kb = 0; kb < 2; kb++) {
                    mma16816(C[n], Ah[kb][0], Ah[kb][1], Ah[kb][2], Ah[kb][3],
                             b1h[n][kb][0], b1h[n][kb][1]);
                    mma16816(C[n], Am[kb][0], Am[kb][1], Am[kb][2], Am[kb][3],
                             b1h[n][kb][0], b1h[n][kb][1]);
                    mma16816(C[n], Ah[kb][0], Ah[kb][1], Ah[kb][2], Ah[kb][3],
                             b1m[n][kb][0], b1m[n][kb][1]);
                }
            }
            #pragma unroll
            for (int n = 0; n < 4; n++) {
                float c0 = fmaxf(C[n][0], 0.f), c1 = fmaxf(C[n][1], 0.f);
                float c2 = fmaxf(C[n][2], 0.f), c3 = fmaxf(C[n][3], 0.f);
                int kb = n >> 1, pos = (n & 1) * 2;
                Ah[kb][pos]     = pack_hi16(c0, c1);
                Ah[kb][pos + 1] = pack_hi16(c2, c3);
                Am[kb][pos]     = pack_rn(c0 - trunc_bf(c0), c1 - trunc_bf(c1));
                Am[kb][pos + 1] = pack_rn(c2 - trunc_bf(c2), c3 - trunc_bf(c3));
            }

            // ---- L2 (K=32) ----
            #pragma unroll
            for (int n = 0; n < 4; n++)
                C[n][0] = C[n][1] = C[n][2] = C[n][3] = 0.f;
            #pragma unroll
            for (int n = 0; n < 4; n++) {
                #pragma unroll
                for (int kb = 0; kb < 2; kb++) {
                    mma16816(C[n], Ah[kb][0], Ah[kb][1], Ah[kb][2], Ah[kb][3],
                             b2h[n][kb][0], b2h[n][kb][1]);
                    mma16816(C[n], Am[kb][0], Am[kb][1], Am[kb][2], Am[kb][3],
                             b2h[n][kb][0], b2h[n][kb][1]);
                    mma16816(C[n], Ah[kb][0], Ah[kb][1], Ah[kb][2], Ah[kb][3],
                             b2m[n][kb][0], b2m[n][kb][1]);
                }
            }
            #pragma unroll
            for (int n = 0; n < 4; n++) {
                float c0 = fmaxf(C[n][0], 0.f), c1 = fmaxf(C[n][1], 0.f);
                float c2 = fmaxf(C[n][2], 0.f), c3 = fmaxf(C[n][3], 0.f);
                int kb = n >> 1, pos = (n & 1) * 2;
                Ah[kb][pos]     = pack_hi16(c0, c1);
                Ah[kb][pos + 1] = pack_hi16(c2, c3);
                Am[kb][pos]     = pack_rn(c0 - trunc_bf(c0), c1 - trunc_bf(c1));
                Am[kb][pos + 1] = pack_rn(c2 - trunc_bf(c2), c3 - trunc_bf(c3));
            }

            // ---- L3 (N=8, col 0 real; K=32): no relu on output ----
            float C4[4];
            C4[0] = C4[1] = C4[2] = C4[3] = 0.f;
            #pragma unroll
            for (int kb = 0; kb < 2; kb++) {
                mma16816(C4, Ah[kb][0], Ah[kb][1], Ah[kb][2], Ah[kb][3],
                         b3h[kb][0], b3h[kb][1]);
                mma16816(C4, Am[kb][0], Am[kb][1], Am[kb][2], Am[kb][3],
                         b3h[kb][0], b3h[kb][1]);
                mma16816(C4, Ah[kb][0], Ah[kb][1], Ah[kb][2], Ah[kb][3],
                         b3m[kb][0], b3m[kb][1]);
            }
            if (q == 0) {   // c0 = (row g, col 0), c2 = (row g+8, col 0)
                long long m0 = obase + mwarp + rbase + g;
                out[m0 * P_ + p]       = C4[0];
                out[(m0 + 8) * P_ + p] = C4[2];
            }
        }
    }
}

extern "C" void kernel_launch(void* const* d_in, const int* in_sizes, int n_in,
                              void* d_out, int out_size)
{
    const float* points   = (const float*)d_in[0];
    const float* features = (const float*)d_in[1];
    const float* W0       = (const float*)d_in[2];
    const float* W1       = (const float*)d_in[3];
    const float* W2       = (const float*)d_in[4];
    const float* W3       = (const float*)d_in[5];
    float* out = (float*)d_out;

    dim3 grid(N_ / CHUNK, P_, B_);
    sdfvae_mma_kernel<<<grid, THREADS>>>(points, features, W0, W1, W2, W3, out);
}

// round 9
// speedup vs baseline: 3.5370x; 1.0990x over previous
#include <cuda_runtime.h>
#include <cuda_bf16.h>
#include <cstdint>

// SDFVae per-part MLP on mma.sync.m16n8k16 (bf16 hi+mid split, f32 accum).
// R9: L3 (N=1) computed as register dot + shfl-reduce instead of MMAs
// (removes 6 MMAs + one full relu/split transition per mt); mid-residual
// packs use PRMT truncation instead of CVT.
//   d_in[0] points [8,42,16384,3] f32   d_in[1] features [8,336] f32
//   d_in[2] W0 [42,32,17]  d_in[3] W1 [42,32,32]
//   d_in[4] W2 [42,32,32]  d_in[5] W3 [42,1,32]
//   out [8,16384,42] f32

#define B_ 8
#define P_ 42
#define N_ 16384
#define THREADS 128
#define CHUNK 2048
#define ITERS (CHUNK / 128)   // 16

__device__ __forceinline__ void mma16816(float c[4],
    uint32_t a0, uint32_t a1, uint32_t a2, uint32_t a3,
    uint32_t b0, uint32_t b1)
{
    asm volatile(
        "mma.sync.aligned.m16n8k16.row.col.f32.bf16.bf16.f32 "
        "{%0,%1,%2,%3}, {%4,%5,%6,%7}, {%8,%9}, {%0,%1,%2,%3};"
        : "+f"(c[0]), "+f"(c[1]), "+f"(c[2]), "+f"(c[3])
        : "r"(a0), "r"(a1), "r"(a2), "r"(a3), "r"(b0), "r"(b1));
}
// bf16x2 {lo,hi} from two f32 (round-to-nearest) — used in one-time weight prep
__device__ __forceinline__ uint32_t pack_rn(float lo, float hi) {
    uint32_t r;
    asm("cvt.rn.satfinite.bf16x2.f32 %0, %1, %2;" : "=r"(r) : "f"(hi), "f"(lo));
    return r;
}
// bf16x2 {lo,hi} by truncating top 16 bits of each f32 (1 PRMT)
__device__ __forceinline__ uint32_t pack_hi16(float lo, float hi) {
    return __byte_perm(__float_as_uint(lo), __float_as_uint(hi), 0x7632);
}
__device__ __forceinline__ float trunc_bf(float v) {
    return __uint_as_float(__float_as_uint(v) & 0xFFFF0000u);
}
__device__ __forceinline__ float rn_bf(float v) {
    return __bfloat162float(__float2bfloat16(v));
}

__global__ __launch_bounds__(THREADS)
void sdfvae_mma_kernel(const float* __restrict__ points,
                       const float* __restrict__ features,
                       const float* __restrict__ W0,
                       const float* __restrict__ W1,
                       const float* __restrict__ W2,
                       const float* __restrict__ W3,
                       float* __restrict__ out)
{
    const int chunk = blockIdx.x, p = blockIdx.y, b = blockIdx.z;
    const int tid = threadIdx.x;
    const int w = tid >> 5, lane = tid & 31;
    const int g = lane >> 2, q = lane & 3;   // groupID, thread-in-group

    // per-warp pe staging: [warp][row][pair] (pairs 0..7 used, pad 9)
    __shared__ uint32_t sPEh[4][32][9];
    __shared__ uint32_t sPEm[4][32][9];

    // ---------------- B fragments (once per CTA, from gmem) ----------------
    // PTX m16n8k16 B (col-major KxN): b0 = {B[2q][n], B[2q+1][n]}, b1 = k+8,
    // n = g (+8*ntile). B[k][n] = W[n][k].
    uint32_t b0h[4][2], b0m[4][2];         // L0  [ntile][b0,b1] (kb=0 only)
    uint32_t b1h[4][2][2], b1m[4][2][2];   // L1  [ntile][kb][b0,b1]
    uint32_t b2h[4][2][2], b2m[4][2][2];   // L2
    float    w3r[4][2];                    // w3[8n+2q], w3[8n+2q+1]

    const float* W0p = W0 + p * 32 * 17;
    const float* fv  = features + (b * P_ + p) * 8;

    #pragma unroll
    for (int j = 0; j < 4; j++) {
        const int n = g + 8 * j;
        const float* w0r = W0p + n * 17;
        float bias = 0.f;
        #pragma unroll
        for (int t = 0; t < 8; t++) bias = fmaf(fv[t], w0r[9 + t], bias);

        // L0 b0: k = 2q, 2q+1  (<= 7, always real pe cols)
        float v0 = w0r[2 * q], v1 = w0r[2 * q + 1];
        b0h[j][0] = pack_rn(rn_bf(v0), rn_bf(v1));
        b0m[j][0] = pack_rn(v0 - rn_bf(v0), v1 - rn_bf(v1));
        // L0 b1: k = 2q+8, 2q+9 : q==0 -> (W0[.,8], bias); q>0 -> k>=10 -> 0
        if (q == 0) {
            float u0 = w0r[8], u1 = bias;
            b0h[j][1] = pack_rn(rn_bf(u0), rn_bf(u1));
            b0m[j][1] = pack_rn(u0 - rn_bf(u0), u1 - rn_bf(u1));
        } else {
            b0h[j][1] = 0u; b0m[j][1] = 0u;
        }

        const float* w1r = W1 + p * 1024 + n * 32;
        const float* w2r = W2 + p * 1024 + n * 32;
        #pragma unroll
        for (int kb = 0; kb < 2; kb++) {
            int k0 = 2 * q + 16 * kb;
            float a0 = w1r[k0], a1 = w1r[k0 + 1], a2 = w1r[k0 + 8], a3 = w1r[k0 + 9];
            b1h[j][kb][0] = pack_rn(rn_bf(a0), rn_bf(a1));
            b1m[j][kb][0] = pack_rn(a0 - rn_bf(a0), a1 - rn_bf(a1));
            b1h[j][kb][1] = pack_rn(rn_bf(a2), rn_bf(a3));
            b1m[j][kb][1] = pack_rn(a2 - rn_bf(a2), a3 - rn_bf(a3));
            float c0 = w2r[k0], c1 = w2r[k0 + 1], c2 = w2r[k0 + 8], c3 = w2r[k0 + 9];
            b2h[j][kb][0] = pack_rn(rn_bf(c0), rn_bf(c1));
            b2m[j][kb][0] = pack_rn(c0 - rn_bf(c0), c1 - rn_bf(c1));
            b2h[j][kb][1] = pack_rn(rn_bf(c2), rn_bf(c3));
            b2m[j][kb][1] = pack_rn(c2 - rn_bf(c2), c3 - rn_bf(c3));
        }
        // L3 weights for the register dot: cols 8j+2q, 8j+2q+1
        w3r[j][0] = W3[p * 32 + 8 * j + 2 * q];
        w3r[j][1] = W3[p * 32 + 8 * j + 2 * q + 1];
    }

    const long long pbase = (long long)(b * P_ + p) * N_ + (long long)chunk * CHUNK;
    const long long obase = (long long)b * N_ + (long long)chunk * CHUNK;

    for (int it = 0; it < ITERS; it++) {
        const int mwarp = it * 128 + w * 32;     // warp's first point (local)

        // ---- pe compute + stage (each lane = its own point = row `lane`) ----
        __syncwarp();
        {
            const float* pt = points + (pbase + mwarp + lane) * 3;
            float x = __ldg(pt), y = __ldg(pt + 1), z = __ldg(pt + 2);
            float v[10];
            v[0] = x; v[1] = y; v[2] = z;
            __sincosf(x, &v[3], &v[6]);
            __sincosf(y, &v[4], &v[7]);
            __sincosf(z, &v[5], &v[8]);
            v[9] = 1.f;   // bias input dim
            #pragma unroll
            for (int t = 0; t < 5; t++) {
                float a = v[2 * t], c = v[2 * t + 1];
                sPEh[w][lane][t] = pack_rn(rn_bf(a), rn_bf(c));
                sPEm[w][lane][t] = pack_rn(a - rn_bf(a), c - rn_bf(c));
            }
            #pragma unroll
            for (int t = 5; t < 8; t++) {
                sPEh[w][lane][t] = 0u;
                sPEm[w][lane][t] = 0u;
            }
        }
        __syncwarp();

        #pragma unroll
        for (int mt = 0; mt < 2; mt++) {
            const int rbase = mt * 16;

            // A0 frags (PTX m16n8k16 A row-major): a0=(g,2q..), a1=(g+8,..),
            // a2=(g, 2q+8..) -> pair q+4, a3=(g+8, pair q+4)
            uint32_t A0h0 = sPEh[w][rbase + g][q];
            uint32_t A0h1 = sPEh[w][rbase + g + 8][q];
            uint32_t A0h2 = sPEh[w][rbase + g][q + 4];
            uint32_t A0h3 = sPEh[w][rbase + g + 8][q + 4];
            uint32_t A0m0 = sPEm[w][rbase + g][q];
            uint32_t A0m1 = sPEm[w][rbase + g + 8][q];
            uint32_t A0m2 = sPEm[w][rbase + g][q + 4];
            uint32_t A0m3 = sPEm[w][rbase + g + 8][q + 4];

            float C[4][4];
            #pragma unroll
            for (int n = 0; n < 4; n++)
                C[n][0] = C[n][1] = C[n][2] = C[n][3] = 0.f;

            // ---- L0 (K=16): 3 split terms ----
            #pragma unroll
            for (int n = 0; n < 4; n++) {
                mma16816(C[n], A0h0, A0h1, A0h2, A0h3, b0h[n][0], b0h[n][1]);
                mma16816(C[n], A0m0, A0m1, A0m2, A0m3, b0h[n][0], b0h[n][1]);
                mma16816(C[n], A0h0, A0h1, A0h2, A0h3, b0m[n][0], b0m[n][1]);
            }

            uint32_t Ah[2][4], Am[2][4];
            // transition: relu + split; C ntile n -> A kb=n/2, regs (n&1)*2..
            #pragma unroll
            for (int n = 0; n < 4; n++) {
                float c0 = fmaxf(C[n][0], 0.f), c1 = fmaxf(C[n][1], 0.f);
                float c2 = fmaxf(C[n][2], 0.f), c3 = fmaxf(C[n][3], 0.f);
                int kb = n >> 1, pos = (n & 1) * 2;
                Ah[kb][pos]     = pack_hi16(c0, c1);
                Ah[kb][pos + 1] = pack_hi16(c2, c3);
                Am[kb][pos]     = pack_hi16(c0 - trunc_bf(c0), c1 - trunc_bf(c1));
                Am[kb][pos + 1] = pack_hi16(c2 - trunc_bf(c2), c3 - trunc_bf(c3));
            }

            // ---- L1 (K=32) ----
            #pragma unroll
            for (int n = 0; n < 4; n++)
                C[n][0] = C[n][1] = C[n][2] = C[n][3] = 0.f;
            #pragma unroll
            for (int n = 0; n < 4; n++) {
                #pragma unroll
                for (int kb = 0; kb < 2; kb++) {
                    mma16816(C[n], Ah[kb][0], Ah[kb][1], Ah[kb][2], Ah[kb][3],
                             b1h[n][kb][0], b1h[n][kb][1]);
                    mma16816(C[n], Am[kb][0], Am[kb][1], Am[kb][2], Am[kb][3],
                             b1h[n][kb][0], b1h[n][kb][1]);
                    mma16816(C[n], Ah[kb][0], Ah[kb][1], Ah[kb][2], Ah[kb][3],
                             b1m[n][kb][0], b1m[n][kb][1]);
                }
            }
            #pragma unroll
            for (int n = 0; n < 4; n++) {
                float c0 = fmaxf(C[n][0], 0.f), c1 = fmaxf(C[n][1], 0.f);
                float c2 = fmaxf(C[n][2], 0.f), c3 = fmaxf(C[n][3], 0.f);
                int kb = n >> 1, pos = (n & 1) * 2;
                Ah[kb][pos]     = pack_hi16(c0, c1);
                Ah[kb][pos + 1] = pack_hi16(c2, c3);
                Am[kb][pos]     = pack_hi16(c0 - trunc_bf(c0), c1 - trunc_bf(c1));
                Am[kb][pos + 1] = pack_hi16(c2 - trunc_bf(c2), c3 - trunc_bf(c3));
            }

            // ---- L2 (K=32) ----
            #pragma unroll
            for (int n = 0; n < 4; n++)
                C[n][0] = C[n][1] = C[n][2] = C[n][3] = 0.f;
            #pragma unroll
            for (int n = 0; n < 4; n++) {
                #pragma unroll
                for (int kb = 0; kb < 2; kb++) {
                    mma16816(C[n], Ah[kb][0], Ah[kb][1], Ah[kb][2], Ah[kb][3],
                             b2h[n][kb][0], b2h[n][kb][1]);
                    mma16816(C[n], Am[kb][0], Am[kb][1], Am[kb][2], Am[kb][3],
                             b2h[n][kb][0], b2h[n][kb][1]);
                    mma16816(C[n], Ah[kb][0], Ah[kb][1], Ah[kb][2], Ah[kb][3],
                             b2m[n][kb][0], b2m[n][kb][1]);
                }
            }

            // ---- L3: relu + per-thread dot with w3, butterfly over q-group ----
            float s0 = 0.f, s1 = 0.f;   // rows g, g+8
            #pragma unroll
            for (int n = 0; n < 4; n++) {
                s0 = fmaf(fmaxf(C[n][0], 0.f), w3r[n][0], s0);
                s0 = fmaf(fmaxf(C[n][1], 0.f), w3r[n][1], s0);
                s1 = fmaf(fmaxf(C[n][2], 0.f), w3r[n][0], s1);
                s1 = fmaf(fmaxf(C[n][3], 0.f), w3r[n][1], s1);
            }
            s0 += __shfl_xor_sync(0xFFFFFFFFu, s0, 1);
            s0 += __shfl_xor_sync(0xFFFFFFFFu, s0, 2);
            s1 += __shfl_xor_sync(0xFFFFFFFFu, s1, 1);
            s1 += __shfl_xor_sync(0xFFFFFFFFu, s1, 2);
            if (q == 0) {
                long long m0 = obase + mwarp + rbase + g;
                out[m0 * P_ + p]       = s0;
                out[(m0 + 8) * P_ + p] = s1;
            }
        }
    }
}

extern "C" void kernel_launch(void* const* d_in, const int* in_sizes, int n_in,
                              void* d_out, int out_size)
{
    const float* points   = (const float*)d_in[0];
    const float* features = (const float*)d_in[1];
    const float* W0       = (const float*)d_in[2];
    const float* W1       = (const float*)d_in[3];
    const float* W2       = (const float*)d_in[4];
    const float* W3       = (const float*)d_in[5];
    float* out = (float*)d_out;

    dim3 grid(N_ / CHUNK, P_, B_);
    sdfvae_mma_kernel<<<grid, THREADS>>>(points, features, W0, W1, W2, W3, out);
}